// round 2
// baseline (speedup 1.0000x reference)
#include <cuda_runtime.h>

// ----------------------------------------------------------------------------
// TGAT edge classifier, restructured:
//   p[n] = h_nodes[n] @ Wm1[0:64]      (node stage)
//   q[n] = h_nodes[n] @ Wm1[64:128]    (node stage)
//   Wz   = [ We @ Wm1[128:192] ; Wm1[192:224] ]   (64x64, prep stage)
//   bc   = bm1 + be @ Wm1[128:192]
//   hidden_e = [ea_e | te_e] @ Wz + p[src_e] + q[dst_e] + bc
//   out_e    = relu(hidden_e) . Wm2 + bm2
// ----------------------------------------------------------------------------

#define N_CAP 100000
#define H 64

__device__ float g_p[N_CAP * H];
__device__ float g_q[N_CAP * H];
__device__ float g_Wz[H * H];
__device__ float g_bc[H];

// ---------------------------------------------------------------- prep ------
__global__ void prep_kernel(const float* __restrict__ We,
                            const float* __restrict__ be,
                            const float* __restrict__ Wm1,
                            const float* __restrict__ bm1) {
    int t = threadIdx.x;  // 256 threads, 1 block
    // Rows 0..31 of Wz: C = We (32x64) @ A3 (64x64), A3 = Wm1 rows 128..191
    for (int idx = t; idx < 32 * 64; idx += 256) {
        int i = idx >> 6, j = idx & 63;
        float s = 0.f;
        for (int k = 0; k < 64; ++k)
            s = fmaf(We[i * 64 + k], Wm1[(128 + k) * 64 + j], s);
        g_Wz[idx] = s;
    }
    // Rows 32..63 of Wz: D = Wm1 rows 192..223 (copy)
    for (int idx = t; idx < 32 * 64; idx += 256) {
        int i = idx >> 6, j = idx & 63;
        g_Wz[(32 + i) * 64 + j] = Wm1[(192 + i) * 64 + j];
    }
    // bc = bm1 + be @ A3
    if (t < 64) {
        float s = bm1[t];
        for (int k = 0; k < 64; ++k)
            s = fmaf(be[k], Wm1[(128 + k) * 64 + t], s);
        g_bc[t] = s;
    }
}

// ------------------------------------------------------------ helpers -------
struct Acc16 { float4 a0, a1, a2, a3; };

// acc(16 outputs, tile jt) += zrow(64) @ W(64x64) column tile
__device__ __forceinline__ void tile_gemm(const float* __restrict__ zrow,
                                          const float* __restrict__ wbase,
                                          int jt, Acc16& A) {
#pragma unroll 8
    for (int k = 0; k < 64; ++k) {
        float zk = zrow[k];
        const float4* w =
            reinterpret_cast<const float4*>(wbase + k * 64 + jt * 16);
        float4 w0 = w[0], w1 = w[1], w2 = w[2], w3 = w[3];
        A.a0.x = fmaf(zk, w0.x, A.a0.x); A.a0.y = fmaf(zk, w0.y, A.a0.y);
        A.a0.z = fmaf(zk, w0.z, A.a0.z); A.a0.w = fmaf(zk, w0.w, A.a0.w);
        A.a1.x = fmaf(zk, w1.x, A.a1.x); A.a1.y = fmaf(zk, w1.y, A.a1.y);
        A.a1.z = fmaf(zk, w1.z, A.a1.z); A.a1.w = fmaf(zk, w1.w, A.a1.w);
        A.a2.x = fmaf(zk, w2.x, A.a2.x); A.a2.y = fmaf(zk, w2.y, A.a2.y);
        A.a2.z = fmaf(zk, w2.z, A.a2.z); A.a2.w = fmaf(zk, w2.w, A.a2.w);
        A.a3.x = fmaf(zk, w3.x, A.a3.x); A.a3.y = fmaf(zk, w3.y, A.a3.y);
        A.a3.z = fmaf(zk, w3.z, A.a3.z); A.a3.w = fmaf(zk, w3.w, A.a3.w);
    }
}

// hout(64 regs) = relu(zrow @ W + b)
__device__ __forceinline__ void layer_relu(const float* __restrict__ zrow,
                                           const float* __restrict__ W,
                                           const float* __restrict__ b,
                                           float* __restrict__ hout) {
#pragma unroll
    for (int jt = 0; jt < 4; ++jt) {
        const float4* bb = reinterpret_cast<const float4*>(b + jt * 16);
        Acc16 A{bb[0], bb[1], bb[2], bb[3]};
        tile_gemm(zrow, W, jt, A);
        float* o = hout + jt * 16;
        o[0]  = fmaxf(A.a0.x, 0.f); o[1]  = fmaxf(A.a0.y, 0.f);
        o[2]  = fmaxf(A.a0.z, 0.f); o[3]  = fmaxf(A.a0.w, 0.f);
        o[4]  = fmaxf(A.a1.x, 0.f); o[5]  = fmaxf(A.a1.y, 0.f);
        o[6]  = fmaxf(A.a1.z, 0.f); o[7]  = fmaxf(A.a1.w, 0.f);
        o[8]  = fmaxf(A.a2.x, 0.f); o[9]  = fmaxf(A.a2.y, 0.f);
        o[10] = fmaxf(A.a2.z, 0.f); o[11] = fmaxf(A.a2.w, 0.f);
        o[12] = fmaxf(A.a3.x, 0.f); o[13] = fmaxf(A.a3.y, 0.f);
        o[14] = fmaxf(A.a3.z, 0.f); o[15] = fmaxf(A.a3.w, 0.f);
    }
}

// dst[0..15] (float4s) = zrow @ W   (no bias, no relu)
__device__ __forceinline__ void proj_store(const float* __restrict__ zrow,
                                           const float* __restrict__ W,
                                           float4* __restrict__ dst) {
#pragma unroll
    for (int jt = 0; jt < 4; ++jt) {
        float4 z4 = make_float4(0.f, 0.f, 0.f, 0.f);
        Acc16 A{z4, z4, z4, z4};
        tile_gemm(zrow, W, jt, A);
        dst[jt * 4 + 0] = A.a0; dst[jt * 4 + 1] = A.a1;
        dst[jt * 4 + 2] = A.a2; dst[jt * 4 + 3] = A.a3;
    }
}

// ------------------------------------------------------------ node stage ----
// smem: W1(4096) W2(4096) A1(4096) A2(4096) b1(64) b2(64) x(128*65)
#define NODE_SMEM_FLOATS (16512 + 128 * 65)
#define NODE_SMEM_BYTES (NODE_SMEM_FLOATS * 4)

__global__ __launch_bounds__(128) void node_kernel(
    const float* __restrict__ x, const float* __restrict__ W1,
    const float* __restrict__ b1, const float* __restrict__ W2,
    const float* __restrict__ b2, const float* __restrict__ Wm1, int N) {
    extern __shared__ float sm[];
    float* sW1 = sm;
    float* sW2 = sm + 4096;
    float* sA1 = sm + 8192;
    float* sA2 = sm + 12288;
    float* sb1 = sm + 16384;
    float* sb2 = sm + 16448;
    float* sx  = sm + 16512;  // 128 rows, stride 65 (bank-conflict-free)
    int t = threadIdx.x;

    for (int i = t; i < 1024; i += 128) {
        reinterpret_cast<float4*>(sW1)[i] = reinterpret_cast<const float4*>(W1)[i];
        reinterpret_cast<float4*>(sW2)[i] = reinterpret_cast<const float4*>(W2)[i];
        reinterpret_cast<float4*>(sA1)[i] = reinterpret_cast<const float4*>(Wm1)[i];
        reinterpret_cast<float4*>(sA2)[i] = reinterpret_cast<const float4*>(Wm1)[1024 + i];
    }
    if (t < 64) { sb1[t] = b1[t]; sb2[t] = b2[t]; }

    int n0 = blockIdx.x * 128;
    // stage x rows (coalesced float4 reads, streaming)
    for (int i = t; i < 128 * 16; i += 128) {
        int r = i >> 4, c = i & 15;
        if (n0 + r < N) {
            float4 v = __ldcs(reinterpret_cast<const float4*>(x) +
                              (size_t)(n0 + r) * 16 + c);
            float* d = sx + r * 65 + c * 4;
            d[0] = v.x; d[1] = v.y; d[2] = v.z; d[3] = v.w;
        }
    }
    __syncthreads();

    int n = n0 + t;
    if (n >= N) return;

    float* zrow = sx + t * 65;  // this thread's private row
    float h[64];

    layer_relu(zrow, sW1, sb1, h);         // h1
#pragma unroll
    for (int j = 0; j < 64; ++j) zrow[j] = h[j];
    layer_relu(zrow, sW2, sb2, h);         // h2 = h_nodes[n]
#pragma unroll
    for (int j = 0; j < 64; ++j) zrow[j] = h[j];

    proj_store(zrow, sA1, reinterpret_cast<float4*>(g_p + (size_t)n * 64));
    proj_store(zrow, sA2, reinterpret_cast<float4*>(g_q + (size_t)n * 64));
}

// ------------------------------------------------------------ edge stage ----
// smem: Wz(4096) bc(64) Wm2(64) z(128*65)
#define EDGE_SMEM_FLOATS (4224 + 128 * 65)
#define EDGE_SMEM_BYTES (EDGE_SMEM_FLOATS * 4)

__global__ __launch_bounds__(128) void edge_kernel(
    const float* __restrict__ ea, const float* __restrict__ te,
    const int* __restrict__ src, const int* __restrict__ dst,
    const float* __restrict__ Wm2, const float* __restrict__ bm2,
    float* __restrict__ out, int E) {
    extern __shared__ float sm[];
    float* sWz  = sm;
    float* sbc  = sm + 4096;
    float* sW2v = sm + 4160;
    float* zs   = sm + 4224;  // 128 rows, stride 65
    int t = threadIdx.x;

    for (int i = t; i < 1024; i += 128)
        reinterpret_cast<float4*>(sWz)[i] = reinterpret_cast<const float4*>(g_Wz)[i];
    if (t < 64) { sbc[t] = g_bc[t]; sW2v[t] = Wm2[t]; }

    int e0 = blockIdx.x * 128;
    // stage z rows = [edge_attr | time_enc], streaming loads (keep p/q in L2)
    for (int i = t; i < 128 * 8; i += 128) {
        int r = i >> 3, c = i & 7;
        if (e0 + r < E) {
            float4 v = __ldcs(reinterpret_cast<const float4*>(ea) +
                              (size_t)(e0 + r) * 8 + c);
            float* d = zs + r * 65 + c * 4;
            d[0] = v.x; d[1] = v.y; d[2] = v.z; d[3] = v.w;
            float4 u = __ldcs(reinterpret_cast<const float4*>(te) +
                              (size_t)(e0 + r) * 8 + c);
            float* d2 = zs + r * 65 + 32 + c * 4;
            d2[0] = u.x; d2[1] = u.y; d2[2] = u.z; d2[3] = u.w;
        }
    }
    __syncthreads();

    int e = e0 + t;
    if (e >= E) return;

    const float* zr = zs + t * 65;
    const float4* pg =
        reinterpret_cast<const float4*>(g_p + (size_t)src[e] * 64);
    const float4* qg =
        reinterpret_cast<const float4*>(g_q + (size_t)dst[e] * 64);
    float acc = bm2[0];

#pragma unroll
    for (int jt = 0; jt < 4; ++jt) {
        const float4* bb = reinterpret_cast<const float4*>(sbc + jt * 16);
        Acc16 A{bb[0], bb[1], bb[2], bb[3]};
        tile_gemm(zr, sWz, jt, A);

        float4 p0 = pg[jt * 4 + 0], p1 = pg[jt * 4 + 1];
        float4 p2 = pg[jt * 4 + 2], p3 = pg[jt * 4 + 3];
        float4 q0 = qg[jt * 4 + 0], q1 = qg[jt * 4 + 1];
        float4 q2 = qg[jt * 4 + 2], q3 = qg[jt * 4 + 3];
        const float4* wm = reinterpret_cast<const float4*>(sW2v + jt * 16);
        float4 m0 = wm[0], m1 = wm[1], m2 = wm[2], m3 = wm[3];

        acc = fmaf(fmaxf(A.a0.x + p0.x + q0.x, 0.f), m0.x, acc);
        acc = fmaf(fmaxf(A.a0.y + p0.y + q0.y, 0.f), m0.y, acc);
        acc = fmaf(fmaxf(A.a0.z + p0.z + q0.z, 0.f), m0.z, acc);
        acc = fmaf(fmaxf(A.a0.w + p0.w + q0.w, 0.f), m0.w, acc);
        acc = fmaf(fmaxf(A.a1.x + p1.x + q1.x, 0.f), m1.x, acc);
        acc = fmaf(fmaxf(A.a1.y + p1.y + q1.y, 0.f), m1.y, acc);
        acc = fmaf(fmaxf(A.a1.z + p1.z + q1.z, 0.f), m1.z, acc);
        acc = fmaf(fmaxf(A.a1.w + p1.w + q1.w, 0.f), m1.w, acc);
        acc = fmaf(fmaxf(A.a2.x + p2.x + q2.x, 0.f), m2.x, acc);
        acc = fmaf(fmaxf(A.a2.y + p2.y + q2.y, 0.f), m2.y, acc);
        acc = fmaf(fmaxf(A.a2.z + p2.z + q2.z, 0.f), m2.z, acc);
        acc = fmaf(fmaxf(A.a2.w + p2.w + q2.w, 0.f), m2.w, acc);
        acc = fmaf(fmaxf(A.a3.x + p3.x + q3.x, 0.f), m3.x, acc);
        acc = fmaf(fmaxf(A.a3.y + p3.y + q3.y, 0.f), m3.y, acc);
        acc = fmaf(fmaxf(A.a3.z + p3.z + q3.z, 0.f), m3.z, acc);
        acc = fmaf(fmaxf(A.a3.w + p3.w + q3.w, 0.f), m3.w, acc);
    }
    out[e] = acc;
}

// ------------------------------------------------------------ launch --------
extern "C" void kernel_launch(void* const* d_in, const int* in_sizes, int n_in,
                              void* d_out, int out_size) {
    const float* x   = (const float*)d_in[0];
    const int*   src = (const int*)d_in[1];
    const int*   dst = (const int*)d_in[2];
    const float* ea  = (const float*)d_in[3];
    const float* te  = (const float*)d_in[4];
    const float* W1  = (const float*)d_in[5];
    const float* b1  = (const float*)d_in[6];
    const float* W2  = (const float*)d_in[7];
    const float* b2  = (const float*)d_in[8];
    const float* We  = (const float*)d_in[9];
    const float* be  = (const float*)d_in[10];
    const float* Wm1 = (const float*)d_in[11];
    const float* bm1 = (const float*)d_in[12];
    const float* Wm2 = (const float*)d_in[13];
    const float* bm2 = (const float*)d_in[14];
    float* out = (float*)d_out;

    int N = in_sizes[0] / 64;
    int E = in_sizes[1];

    // One-time host-side setup; kept off the graph-capture call path so the
    // captured sequence is kernel launches only.
    static bool attrs_set = false;
    if (!attrs_set) {
        cudaFuncSetAttribute(node_kernel,
                             cudaFuncAttributeMaxDynamicSharedMemorySize,
                             NODE_SMEM_BYTES);
        cudaFuncSetAttribute(edge_kernel,
                             cudaFuncAttributeMaxDynamicSharedMemorySize,
                             EDGE_SMEM_BYTES);
        attrs_set = true;
    }

    prep_kernel<<<1, 256>>>(We, be, Wm1, bm1);
    node_kernel<<<(N + 127) / 128, 128, NODE_SMEM_BYTES>>>(x, W1, b1, W2, b2,
                                                           Wm1, N);
    edge_kernel<<<(E + 127) / 128, 128, EDGE_SMEM_BYTES>>>(ea, te, src, dst,
                                                           Wm2, bm2, out, E);
}